// round 6
// baseline (speedup 1.0000x reference)
#include <cuda_runtime.h>
#include <cuda_bf16.h>
#include <cstdint>

#define NUM_TAGS 48
#define SEQ_LEN  512
#define BATCH    1024
#define CHUNK    8
#define HALF     256
#define NCH      (HALF / CHUNK)     // 32 chunks per half

__device__ float    g_nll[BATCH];
__device__ unsigned g_count = 0;

// ---- packed f32x2 helpers (Blackwell FFMA2 path, PTX-only) ------------------
__device__ __forceinline__ void fma2(uint64_t& d, uint64_t a, uint64_t b) {
    asm("fma.rn.f32x2 %0, %1, %2, %0;" : "+l"(d) : "l"(a), "l"(b));
}
__device__ __forceinline__ uint64_t add2(uint64_t a, uint64_t b) {
    uint64_t d;
    asm("add.rn.f32x2 %0, %1, %2;" : "=l"(d) : "l"(a), "l"(b));
    return d;
}
__device__ __forceinline__ uint64_t pack2(float lo, float hi) {
    uint64_t d;
    asm("mov.b64 %0, {%1, %2};" : "=l"(d) : "f"(lo), "f"(hi));
    return d;
}
__device__ __forceinline__ float lo2(uint64_t v) { return __uint_as_float((uint32_t)v); }
__device__ __forceinline__ float hi2(uint64_t v) { return __uint_as_float((uint32_t)(v >> 32)); }

__device__ __forceinline__ void cp16(uint32_t saddr, const void* g) {
    asm volatile("cp.async.cg.shared.global [%0], [%1], 16;" :: "r"(saddr), "l"(g));
}

// One CTA (2 warps) per batch element: warp 0 runs the forward half t=[0,256),
// warp 1 runs the backward (transpose) half t=[256,512). Exact split:
//   logZ = C_f + C_b + log( v_hat . w_hat )
__global__ __launch_bounds__(64)
void crf_fused_kernel(const float* __restrict__ emissions,
                      const float* __restrict__ transitions,
                      const int*   __restrict__ tags,
                      const int*   __restrict__ mask,
                      float*       __restrict__ out)
{
    const int tid  = threadIdx.x;
    const int lane = tid & 31;
    const int wid  = tid >> 5;
    const int b    = blockIdx.x;
    const int h    = lane >> 4;     // 24-input half: i/j in [24h, 24h+24)
    const int q    = lane & 15;     // owned triple {3q,3q+1,3q+2}
    const int j0   = 3 * q;
    const int i0   = 24 * h;

    __shared__ __align__(16) float swbuf[2][2][NUM_TAGS];        // [warp][pp][48]
    __shared__ __align__(16) float sem[2][2][CHUNK * NUM_TAGS];  // [warp][pp][384]
    __shared__ int   stags[SEQ_LEN];
    __shared__ int   smask[SEQ_LEN];
    __shared__ float sres[2][NUM_TAGS];
    __shared__ float sC[2], ssc[2];

    const float* em_b   = emissions + (size_t)b * SEQ_LEN * NUM_TAGS;
    const int*   tags_b = tags + b * SEQ_LEN;
    const int*   mask_b = mask + b * SEQ_LEN;

    // --- stage chunk 0 for this warp (fwd: rows 0..7, bwd: rows 504..511) -----
    {
        const float* src = em_b + (wid == 0 ? 0 : (size_t)(SEQ_LEN - CHUNK) * NUM_TAGS);
        uint32_t dst = (uint32_t)__cvta_generic_to_shared(&sem[wid][0][0]);
        #pragma unroll
        for (int r = 0; r < 3; r++)
            cp16(dst + lane * 16 + r * 512, src + lane * 4 + r * 128);
        asm volatile("cp.async.commit_group;");
    }

    // --- tags / mask cooperatively (64 threads, int4) ---------------------------
    #pragma unroll
    for (int r = 0; r < 2; r++) {
        ((int4*)stags)[tid + 64 * r] = ((const int4*)tags_b)[tid + 64 * r];
        ((int4*)smask)[tid + 64 * r] = ((const int4*)mask_b)[tid + 64 * r];
    }
    __syncthreads();

    if (wid == 0) {
        // ================= FORWARD HALF: w <- (E^T w) . exp(e_t) ================
        // Ec[c][pair k]: columns j0+c of E, input rows i0+2k, i0+2k+1
        uint64_t Ec[36];
        #pragma unroll
        for (int c = 0; c < 3; c++)
            #pragma unroll
            for (int k = 0; k < 12; k++)
                Ec[c * 12 + k] = pack2(__expf(transitions[(i0 + 2 * k    ) * NUM_TAGS + j0 + c]),
                                       __expf(transitions[(i0 + 2 * k + 1) * NUM_TAGS + j0 + c]));

        float w0 = (q == 0) ? 1.0f : 0.0f, w1 = 0.0f, w2 = 0.0f;
        if (h == 0) {
            swbuf[0][0][j0] = w0; swbuf[0][0][j0 + 1] = w1; swbuf[0][0][j0 + 2] = w2;
        }
        __syncwarp();

        // gold-path score, t in [1,256)
        float sc = 0.0f;
        #pragma unroll 4
        for (int t = 1 + lane; t < HALF; t += 32) {
            int tc = stags[t], tp = stags[t - 1];
            if (smask[t])
                sc += em_b[(size_t)t * NUM_TAGS + tc] + transitions[tp * NUM_TAGS + tc];
        }
        #pragma unroll
        for (int off = 16; off; off >>= 1)
            sc += __shfl_xor_sync(0xffffffffu, sc, off);

        float C = 0.0f;
        for (int c = 0; c < NCH; c++) {
            if (c + 1 < NCH) {
                uint32_t dst = (uint32_t)__cvta_generic_to_shared(&sem[0][(c + 1) & 1][0]);
                const float* src = em_b + (size_t)(c + 1) * CHUNK * NUM_TAGS;
                #pragma unroll
                for (int r = 0; r < 3; r++)
                    cp16(dst + lane * 16 + r * 512, src + lane * 4 + r * 128);
            }
            asm volatile("cp.async.commit_group;");
            asm volatile("cp.async.wait_group 1;");
            __syncwarp();

            const float* eb = sem[0][c & 1];
            const int*   mb = smask + c * CHUNK;

            float eE[CHUNK][3];
            #pragma unroll
            for (int u = 0; u < CHUNK; u++) {
                eE[u][0] = __expf(eb[u * NUM_TAGS + j0]);
                eE[u][1] = __expf(eb[u * NUM_TAGS + j0 + 1]);
                eE[u][2] = __expf(eb[u * NUM_TAGS + j0 + 2]);
            }

            #pragma unroll
            for (int u = 0; u < CHUNK; u++) {
                const ulonglong2* wv = (const ulonglong2*)(&swbuf[0][u & 1][i0]);
                uint64_t a0[3] = {0, 0, 0}, a1[3] = {0, 0, 0};
                #pragma unroll
                for (int r = 0; r < 6; r++) {
                    ulonglong2 W = wv[r];
                    #pragma unroll
                    for (int cc = 0; cc < 3; cc++) {
                        fma2(a0[cc], W.x, Ec[cc * 12 + 2 * r]);
                        fma2(a1[cc], W.y, Ec[cc * 12 + 2 * r + 1]);
                    }
                }
                int m = mb[u];
                float nv[3];
                #pragma unroll
                for (int cc = 0; cc < 3; cc++) {
                    uint64_t s = add2(a0[cc], a1[cc]);
                    float d = lo2(s) + hi2(s);
                    d += __shfl_xor_sync(0xffffffffu, d, 16);
                    nv[cc] = d * eE[u][cc];
                }
                w0 = m ? nv[0] : w0;
                w1 = m ? nv[1] : w1;
                w2 = m ? nv[2] : w2;
                if (h == 0) {
                    float* wd = swbuf[0][(u & 1) ^ 1];
                    wd[j0] = w0; wd[j0 + 1] = w1; wd[j0 + 2] = w2;
                }
                __syncwarp();
            }

            float v = (h == 0) ? (w0 + w1 + w2) : 0.0f;
            #pragma unroll
            for (int off = 16; off; off >>= 1)
                v += __shfl_xor_sync(0xffffffffu, v, off);
            C += __logf(v);
            float inv = 1.0f / v;
            w0 *= inv; w1 *= inv; w2 *= inv;
            if (h == 0) {
                swbuf[0][0][j0] = w0; swbuf[0][0][j0 + 1] = w1; swbuf[0][0][j0 + 2] = w2;
            }
            __syncwarp();
        }

        if (h == 0) {
            sres[0][j0] = w0; sres[0][j0 + 1] = w1; sres[0][j0 + 2] = w2;
        }
        if (lane == 0) {
            sC[0]  = C;
            ssc[0] = sc + em_b[stags[0]];   // emit[0] always counted
        }
    } else {
        // ================ BACKWARD HALF: v <- E (exp(e_t) . v), t = 511..256 ====
        // Er[c][pair k]: row 3q+c of E, input cols i0+2k, i0+2k+1 (contiguous)
        uint64_t Er[36];
        #pragma unroll
        for (int c = 0; c < 3; c++)
            #pragma unroll
            for (int k = 0; k < 12; k++)
                Er[c * 12 + k] = pack2(__expf(transitions[(3 * q + c) * NUM_TAGS + i0 + 2 * k]),
                                       __expf(transitions[(3 * q + c) * NUM_TAGS + i0 + 2 * k + 1]));

        float v0 = 1.0f, v1 = 1.0f, v2 = 1.0f;   // v starts as all-ones

        // gold-path score, t in [256,512)
        float sc = 0.0f;
        #pragma unroll 4
        for (int t = HALF + lane; t < SEQ_LEN; t += 32) {
            int tc = stags[t], tp = stags[t - 1];
            if (smask[t])
                sc += em_b[(size_t)t * NUM_TAGS + tc] + transitions[tp * NUM_TAGS + tc];
        }
        #pragma unroll
        for (int off = 16; off; off >>= 1)
            sc += __shfl_xor_sync(0xffffffffu, sc, off);

        float C = 0.0f;
        for (int c = 0; c < NCH; c++) {
            const int Tb = SEQ_LEN - CHUNK * (c + 1);     // chunk covers t = Tb..Tb+7
            if (c + 1 < NCH) {
                uint32_t dst = (uint32_t)__cvta_generic_to_shared(&sem[1][(c + 1) & 1][0]);
                const float* src = em_b + (size_t)(Tb - CHUNK) * NUM_TAGS;
                #pragma unroll
                for (int r = 0; r < 3; r++)
                    cp16(dst + lane * 16 + r * 512, src + lane * 4 + r * 128);
            }
            asm volatile("cp.async.commit_group;");
            asm volatile("cp.async.wait_group 1;");
            __syncwarp();

            const float* eb = sem[1][c & 1];

            // boundary scale exp(e[Tb-1]) from global (off-chain; unused at c=NCH-1)
            float eEp[3];
            {
                const float* gp = em_b + (size_t)(Tb - 1) * NUM_TAGS + j0;
                eEp[0] = __expf(__ldg(gp));
                eEp[1] = __expf(__ldg(gp + 1));
                eEp[2] = __expf(__ldg(gp + 2));
            }
            float eE[CHUNK][3];
            #pragma unroll
            for (int u = 0; u < CHUNK; u++) {
                eE[u][0] = __expf(eb[u * NUM_TAGS + j0]);
                eE[u][1] = __expf(eb[u * NUM_TAGS + j0 + 1]);
                eE[u][2] = __expf(eb[u * NUM_TAGS + j0 + 2]);
            }

            if (c == 0) {   // init y_511 = exp(e_511) . 1
                if (h == 0) {
                    swbuf[1][0][j0]     = eE[7][0];
                    swbuf[1][0][j0 + 1] = eE[7][1];
                    swbuf[1][0][j0 + 2] = eE[7][2];
                }
                __syncwarp();
            }

            #pragma unroll
            for (int s = 0; s < CHUNK; s++) {
                const int u = CHUNK - 1 - s;               // consume t = Tb+u, descending
                const ulonglong2* yv = (const ulonglong2*)(&swbuf[1][s & 1][i0]);
                uint64_t a0[3] = {0, 0, 0}, a1[3] = {0, 0, 0};
                #pragma unroll
                for (int r = 0; r < 6; r++) {
                    ulonglong2 Y = yv[r];
                    #pragma unroll
                    for (int cc = 0; cc < 3; cc++) {
                        fma2(a0[cc], Y.x, Er[cc * 12 + 2 * r]);
                        fma2(a1[cc], Y.y, Er[cc * 12 + 2 * r + 1]);
                    }
                }
                int m = smask[Tb + u];
                float nv[3];
                #pragma unroll
                for (int cc = 0; cc < 3; cc++) {
                    uint64_t ss = add2(a0[cc], a1[cc]);
                    float d = lo2(ss) + hi2(ss);
                    d += __shfl_xor_sync(0xffffffffu, d, 16);
                    nv[cc] = d;
                }
                v0 = m ? nv[0] : v0;
                v1 = m ? nv[1] : v1;
                v2 = m ? nv[2] : v2;
                // store y = exp(e_{t-1}) . v  (scale for the NEXT consumed step)
                float s0 = (u > 0) ? eE[u - 1][0] : eEp[0];
                float s1 = (u > 0) ? eE[u - 1][1] : eEp[1];
                float s2 = (u > 0) ? eE[u - 1][2] : eEp[2];
                if (h == 0) {
                    float* yd = swbuf[1][(s & 1) ^ 1];
                    yd[j0] = s0 * v0; yd[j0 + 1] = s1 * v1; yd[j0 + 2] = s2 * v2;
                }
                __syncwarp();
            }

            // renormalize raw v; rewrite scaled y consistently
            float vs = (h == 0) ? (v0 + v1 + v2) : 0.0f;
            #pragma unroll
            for (int off = 16; off; off >>= 1)
                vs += __shfl_xor_sync(0xffffffffu, vs, off);
            C += __logf(vs);
            float inv = 1.0f / vs;
            v0 *= inv; v1 *= inv; v2 *= inv;
            if (h == 0) {
                swbuf[1][0][j0]     = eEp[0] * v0;
                swbuf[1][0][j0 + 1] = eEp[1] * v1;
                swbuf[1][0][j0 + 2] = eEp[2] * v2;
            }
            __syncwarp();
        }

        if (h == 0) {
            sres[1][j0] = v0; sres[1][j0 + 1] = v1; sres[1][j0 + 2] = v2;
        }
        if (lane == 0) {
            sC[1]  = C;
            ssc[1] = sc;
        }
    }

    // --- combine halves: logZ = C_f + C_b + log(v_hat . w_hat) ------------------
    __syncthreads();
    if (wid == 0) {
        float d = 0.0f;
        if (h == 0) {
            d = sres[0][j0]     * sres[1][j0]
              + sres[0][j0 + 1] * sres[1][j0 + 1]
              + sres[0][j0 + 2] * sres[1][j0 + 2];
        }
        #pragma unroll
        for (int off = 16; off; off >>= 1)
            d += __shfl_xor_sync(0xffffffffu, d, off);
        if (lane == 0) {
            float logZ = sC[0] + sC[1] + __logf(d);
            g_nll[b] = logZ - (ssc[0] + ssc[1]);
        }
    }

    // --- fused mean-reduce: last CTA does the deterministic sum ------------------
    __syncthreads();
    __shared__ unsigned sdone;
    if (tid == 0) {
        __threadfence();
        sdone = atomicAdd(&g_count, 1u);
    }
    __syncthreads();
    if (sdone == BATCH - 1 && wid == 0) {
        __threadfence();
        float v = 0.0f;
        #pragma unroll
        for (int i = lane; i < BATCH; i += 32)
            v += __ldcg(&g_nll[i]);
        #pragma unroll
        for (int off = 16; off; off >>= 1)
            v += __shfl_xor_sync(0xffffffffu, v, off);
        if (lane == 0) {
            out[0] = v * (1.0f / (float)BATCH);
            g_count = 0;   // reset for next graph replay
        }
    }
}

extern "C" void kernel_launch(void* const* d_in, const int* in_sizes, int n_in,
                              void* d_out, int out_size)
{
    const float* emissions   = (const float*)d_in[0];
    const float* transitions = (const float*)d_in[1];
    const int*   tags        = (const int*)d_in[2];
    const int*   mask        = (const int*)d_in[3];
    float*       out         = (float*)d_out;

    crf_fused_kernel<<<BATCH, 64>>>(emissions, transitions, tags, mask, out);
}

// round 7
// speedup vs baseline: 1.2984x; 1.2984x over previous
#include <cuda_runtime.h>
#include <cuda_bf16.h>
#include <cstdint>

#define NUM_TAGS 48
#define SEQ_LEN  512
#define BATCH    1024
#define CHUNK    8
#define NCHUNK   (SEQ_LEN / CHUNK)   // 64

__device__ float    g_nll[BATCH];
__device__ unsigned g_count = 0;

// ---- packed f32x2 helpers (Blackwell FFMA2 path, PTX-only) ------------------
__device__ __forceinline__ void fma2(uint64_t& d, uint64_t a, uint64_t b) {
    asm("fma.rn.f32x2 %0, %1, %2, %0;" : "+l"(d) : "l"(a), "l"(b));
}
__device__ __forceinline__ uint64_t add2(uint64_t a, uint64_t b) {
    uint64_t d;
    asm("add.rn.f32x2 %0, %1, %2;" : "=l"(d) : "l"(a), "l"(b));
    return d;
}
__device__ __forceinline__ uint64_t pack2(float lo, float hi) {
    uint64_t d;
    asm("mov.b64 %0, {%1, %2};" : "=l"(d) : "f"(lo), "f"(hi));
    return d;
}
__device__ __forceinline__ float lo2(uint64_t v) { return __uint_as_float((uint32_t)v); }
__device__ __forceinline__ float hi2(uint64_t v) { return __uint_as_float((uint32_t)(v >> 32)); }

__device__ __forceinline__ void cp16(uint32_t saddr, const void* g) {
    asm volatile("cp.async.cg.shared.global [%0], [%1], 16;" :: "r"(saddr), "l"(g));
}

// One warp (one CTA) per batch element. Step loop is warp-synchronous with NO
// WARPSYNC: the full-mask shfl_xor each step anchors convergence; all 32 lanes
// store bit-identical values (lane q and q+16 duplicates) so the write is
// deterministic; STS->LDS on the same buffer preserves ordering.
__global__ __launch_bounds__(32)
void crf_fused_kernel(const float* __restrict__ emissions,
                      const float* __restrict__ transitions,
                      const int*   __restrict__ tags,
                      const int*   __restrict__ mask,
                      float*       __restrict__ out)
{
    const int lane = threadIdx.x;
    const int b    = blockIdx.x;
    const int h    = lane >> 4;     // input half: i in [24h, 24h+24)
    const int q    = lane & 15;     // owned output triple {3q,3q+1,3q+2}
    const int j0   = 3 * q;
    const int i0   = 24 * h;

    __shared__ __align__(16) float swbuf[2][NUM_TAGS];        // alpha ping-pong
    __shared__ __align__(16) float sem[2][CHUNK * NUM_TAGS];  // emission chunks
    __shared__ int stags[SEQ_LEN];
    __shared__ int smask[SEQ_LEN];

    const float* em_b   = emissions + (size_t)b * SEQ_LEN * NUM_TAGS;
    const int*   tags_b = tags + b * SEQ_LEN;
    const int*   mask_b = mask + b * SEQ_LEN;

    // --- stage emission chunk 0 -------------------------------------------------
    {
        uint32_t dst = (uint32_t)__cvta_generic_to_shared(&sem[0][0]);
        #pragma unroll
        for (int r = 0; r < 3; r++)
            cp16(dst + lane * 16 + r * 512, em_b + lane * 4 + r * 128);
        asm volatile("cp.async.commit_group;");
    }

    // --- tags / mask to shared (vectorized) --------------------------------------
    #pragma unroll
    for (int r = 0; r < 4; r++) {
        ((int4*)stags)[lane + 32 * r] = ((const int4*)tags_b)[lane + 32 * r];
        ((int4*)smask)[lane + 32 * r] = ((const int4*)mask_b)[lane + 32 * r];
    }

    // --- E = exp(T): half-column slices, 3 output cols per lane -------------------
    uint64_t Ec[36];
    #pragma unroll
    for (int c = 0; c < 3; c++)
        #pragma unroll
        for (int k = 0; k < 12; k++)
            Ec[c * 12 + k] = pack2(__expf(transitions[(i0 + 2 * k    ) * NUM_TAGS + j0 + c]),
                                   __expf(transitions[(i0 + 2 * k + 1) * NUM_TAGS + j0 + c]));

    // --- init alphas (linear): only tag 0 live ------------------------------------
    float w0 = (q == 0) ? 1.0f : 0.0f;
    float w1 = 0.0f, w2 = 0.0f;
    swbuf[0][j0]     = w0;    // all lanes store (q / q+16 duplicates, identical)
    swbuf[0][j0 + 1] = w1;
    swbuf[0][j0 + 2] = w2;
    __syncwarp();

    // --- gold-path score (overlaps staged chunk-0 latency) -------------------------
    float sc = 0.0f;
    #pragma unroll 4
    for (int t = 1 + lane; t < SEQ_LEN; t += 32) {
        int tc = stags[t], tp = stags[t - 1];
        if (smask[t])
            sc += em_b[(size_t)t * NUM_TAGS + tc] + transitions[tp * NUM_TAGS + tc];
    }
    #pragma unroll
    for (int off = 16; off; off >>= 1)
        sc += __shfl_xor_sync(0xffffffffu, sc, off);

    // --- forward recursion: 64 chunks x 8 steps -------------------------------------
    // Invariant at chunk entry: registers w* / swbuf hold values UNSCALED by
    // carry_inv; C holds all accumulated logs; carry_inv is pending.
    float C = 0.0f;
    float carry_inv = 1.0f;

    for (int c = 0; c < NCHUNK; c++) {
        if (c + 1 < NCHUNK) {
            uint32_t dst = (uint32_t)__cvta_generic_to_shared(&sem[(c + 1) & 1][0]);
            const float* src = em_b + (size_t)(c + 1) * CHUNK * NUM_TAGS;
            #pragma unroll
            for (int r = 0; r < 3; r++)
                cp16(dst + lane * 16 + r * 512, src + lane * 4 + r * 128);
        }
        asm volatile("cp.async.commit_group;");
        asm volatile("cp.async.wait_group 1;");
        __syncwarp();

        const float* eb = sem[c & 1];

        // hoist emission exps for this chunk (off the recurrence chain)
        float eE[CHUNK][3];
        #pragma unroll
        for (int u = 0; u < CHUNK; u++) {
            eE[u][0] = __expf(eb[u * NUM_TAGS + j0]);
            eE[u][1] = __expf(eb[u * NUM_TAGS + j0 + 1]);
            eE[u][2] = __expf(eb[u * NUM_TAGS + j0 + 2]);
        }

        // uniform mask test for this chunk
        const int4 ma = ((const int4*)(smask + c * CHUNK))[0];
        const int4 mb = ((const int4*)(smask + c * CHUNK))[1];
        const int mall = ma.x & ma.y & ma.z & ma.w & mb.x & mb.y & mb.z & mb.w;

        if (mall) {
            // fast path: no selects, no syncwarp; pending scale folded into step 0
            eE[0][0] *= carry_inv; eE[0][1] *= carry_inv; eE[0][2] *= carry_inv;

            #pragma unroll
            for (int u = 0; u < CHUNK; u++) {
                const ulonglong2* wv = (const ulonglong2*)(&swbuf[u & 1][i0]);
                uint64_t a0[3] = {0, 0, 0}, a1[3] = {0, 0, 0};
                #pragma unroll
                for (int r = 0; r < 6; r++) {
                    ulonglong2 W = wv[r];
                    #pragma unroll
                    for (int cc = 0; cc < 3; cc++) {
                        fma2(a0[cc], W.x, Ec[cc * 12 + 2 * r]);
                        fma2(a1[cc], W.y, Ec[cc * 12 + 2 * r + 1]);
                    }
                }
                float* wd = swbuf[(u & 1) ^ 1];
                #pragma unroll
                for (int cc = 0; cc < 3; cc++) {
                    uint64_t s = add2(a0[cc], a1[cc]);
                    float d = lo2(s) + hi2(s);                  // own half-dot
                    d += __shfl_xor_sync(0xffffffffu, d, 16);   // symmetric combine
                    d *= eE[u][cc];                             // bit-identical in pair
                    if (cc == 0) w0 = d; else if (cc == 1) w1 = d; else w2 = d;
                    wd[j0 + cc] = d;                            // all lanes store
                }
                asm volatile("" ::: "memory");
            }
        } else {
            // slow path (general mask): apply pending scale, then select-based steps
            w0 *= carry_inv; w1 *= carry_inv; w2 *= carry_inv;
            carry_inv = 1.0f;
            swbuf[0][j0] = w0; swbuf[0][j0 + 1] = w1; swbuf[0][j0 + 2] = w2;
            __syncwarp();

            #pragma unroll
            for (int u = 0; u < CHUNK; u++) {
                const ulonglong2* wv = (const ulonglong2*)(&swbuf[u & 1][i0]);
                uint64_t a0[3] = {0, 0, 0}, a1[3] = {0, 0, 0};
                #pragma unroll
                for (int r = 0; r < 6; r++) {
                    ulonglong2 W = wv[r];
                    #pragma unroll
                    for (int cc = 0; cc < 3; cc++) {
                        fma2(a0[cc], W.x, Ec[cc * 12 + 2 * r]);
                        fma2(a1[cc], W.y, Ec[cc * 12 + 2 * r + 1]);
                    }
                }
                int m = smask[c * CHUNK + u];
                float nv[3];
                #pragma unroll
                for (int cc = 0; cc < 3; cc++) {
                    uint64_t s = add2(a0[cc], a1[cc]);
                    float d = lo2(s) + hi2(s);
                    d += __shfl_xor_sync(0xffffffffu, d, 16);
                    nv[cc] = d * eE[u][cc];
                }
                w0 = m ? nv[0] : w0;
                w1 = m ? nv[1] : w1;
                w2 = m ? nv[2] : w2;
                float* wd = swbuf[(u & 1) ^ 1];
                wd[j0] = w0; wd[j0 + 1] = w1; wd[j0 + 2] = w2;
                __syncwarp();
            }
        }

        // lazy renorm: any positive scale is exact once logged; use alpha[0]
        float s = __shfl_sync(0xffffffffu, w0, 0);   // > 0 always
        C += __logf(s);
        carry_inv = __fdividef(1.0f, s);
    }

    // --- final partition: logZ = C + log( (sum w) * carry_inv ) ---------------------
    float v = (h == 0) ? (w0 + w1 + w2) : 0.0f;
    #pragma unroll
    for (int off = 16; off; off >>= 1)
        v += __shfl_xor_sync(0xffffffffu, v, off);
    if (lane == 0) {
        float logZ  = C + __logf(v * carry_inv);
        float score = sc + em_b[stags[0]];           // emit[0] always counted
        g_nll[b] = logZ - score;
    }

    // --- fused mean-reduce: last CTA does the deterministic sum ---------------------
    unsigned done = 0;
    if (lane == 0) {
        __threadfence();
        done = atomicAdd(&g_count, 1u);
    }
    done = __shfl_sync(0xffffffffu, done, 0);
    if (done == BATCH - 1) {
        __threadfence();
        float r = 0.0f;
        #pragma unroll
        for (int i = lane; i < BATCH; i += 32)
            r += __ldcg(&g_nll[i]);
        #pragma unroll
        for (int off = 16; off; off >>= 1)
            r += __shfl_xor_sync(0xffffffffu, r, off);
        if (lane == 0) {
            out[0] = r * (1.0f / (float)BATCH);
            g_count = 0;   // reset for next graph replay
        }
    }
}

extern "C" void kernel_launch(void* const* d_in, const int* in_sizes, int n_in,
                              void* d_out, int out_size)
{
    const float* emissions   = (const float*)d_in[0];
    const float* transitions = (const float*)d_in[1];
    const int*   tags        = (const int*)d_in[2];
    const int*   mask        = (const int*)d_in[3];
    float*       out         = (float*)d_out;

    crf_fused_kernel<<<BATCH, 32>>>(emissions, transitions, tags, mask, out);
}